// round 14
// baseline (speedup 1.0000x reference)
#include <cuda_runtime.h>
#include <cuda_fp16.h>
#include <cstdint>

#define N_NODES 100000
#define N_EDGES 3200000
#define D_IN    128
#define D_OUT   64
#define CAP     96      // max in-degree bucket capacity (actual max ~58 for Poisson(32))

// ---------------- scratch (static device globals; no allocation) ----------------
__device__ unsigned g_zh  [(size_t)N_NODES * 32];      // z as half2 (64 cols -> 32 words), 12.8 MB
__device__ float    g_ezs [N_NODES];                   // exp(h . va)  (zd cancels in softmax)
__device__ int      g_cnt [N_NODES];                   // bucket fill counts
__device__ int2     g_perm[(size_t)N_NODES * CAP];     // (src, bitcast(w)) buckets, 76.8 MB
__device__ uint2    g_wf  [8 * 8 * 32];                // W as HMMA B-fragments [kstep][ntile][lane]
__device__ float    g_va  [D_IN];                      // W @ a[:64]

// ---------------- K0: prep — W fragments + projected attention vector ----------------
__global__ void k_prep(const float* __restrict__ W, const float* __restrict__ a) {
    if (blockIdx.x < 8) {
        int t = blockIdx.x * 256 + threadIdx.x;       // 0..2047 = [kstep][ntile][lane]
        int lane = t & 31;
        int gid = lane >> 2, tig = lane & 3;
        int rest = t >> 5;
        int ntile = rest & 7, kstep = rest >> 3;
        int k0 = kstep * 16 + tig * 2;
        int n  = ntile * 8 + gid;
        __half2 b0 = __floats2half2_rn(W[k0 * 64 + n],       W[(k0 + 1) * 64 + n]);
        __half2 b1 = __floats2half2_rn(W[(k0 + 8) * 64 + n], W[(k0 + 9) * 64 + n]);
        g_wf[t] = make_uint2(*(unsigned*)&b0, *(unsigned*)&b1);
    } else {
        int k = threadIdx.x;
        if (k < D_IN) {
            float sa = 0.0f;
            #pragma unroll 8
            for (int n = 0; n < 64; ++n)
                sa = fmaf(W[k * 64 + n], a[n], sa);
            g_va[k] = sa;
        }
    }
}

// ---------------- K1a: logits — ezs = exp(h . va); zero cnt (warp per node) ----------
__global__ __launch_bounds__(256) void k_logit(const float* __restrict__ h) {
    int gw   = (blockIdx.x * 256 + threadIdx.x) >> 5;
    int lane = threadIdx.x & 31;
    if (gw >= N_NODES) return;
    float4 v  = ((const float4*)(h + (size_t)gw * D_IN))[lane];
    float4 va = ((const float4*)g_va)[lane];
    float s = v.x * va.x + v.y * va.y + v.z * va.z + v.w * va.w;
    #pragma unroll
    for (int o = 16; o > 0; o >>= 1)
        s += __shfl_xor_sync(0xffffffffu, s, o);
    if (lane == 0) {
        g_ezs[gw] = __expf(s);
        g_cnt[gw] = 0;
    }
}

// ---------------- K1b: z = h @ W via HMMA m16n8k16 (parallel branch) ------------------
// 8 warps/block, warp = 16 nodes x 64 cols. A frags straight from gmem (fp32->f16x2).
__global__ __launch_bounds__(256) void k_gemm(const float* __restrict__ h) {
    int warp = threadIdx.x >> 5, lane = threadIdx.x & 31;
    int gid = lane >> 2, tig = lane & 3;
    int M0 = blockIdx.x * 128 + warp * 16;
    if (M0 >= N_NODES) return;                         // 100000 % 16 == 0: full tiles only
    const float* rowA = h + (size_t)(M0 + gid) * D_IN;
    const float* rowB = h + (size_t)(M0 + 8 + gid) * D_IN;

    float d[8][4] = {};                                // [ntile][c0..c3]

    #pragma unroll
    for (int ks = 0; ks < 8; ++ks) {
        int kA = ks * 16 + tig * 2;
        float2 fa0 = *(const float2*)&rowA[kA];
        float2 fa1 = *(const float2*)&rowB[kA];
        float2 fa2 = *(const float2*)&rowA[kA + 8];
        float2 fa3 = *(const float2*)&rowB[kA + 8];
        __half2 ha0 = __floats2half2_rn(fa0.x, fa0.y);
        __half2 ha1 = __floats2half2_rn(fa1.x, fa1.y);
        __half2 ha2 = __floats2half2_rn(fa2.x, fa2.y);
        __half2 ha3 = __floats2half2_rn(fa3.x, fa3.y);
        unsigned a0 = *(unsigned*)&ha0, a1 = *(unsigned*)&ha1;
        unsigned a2 = *(unsigned*)&ha2, a3 = *(unsigned*)&ha3;
        const uint2* wf = &g_wf[ks * 256 + lane];
        #pragma unroll
        for (int nt = 0; nt < 8; ++nt) {
            uint2 b = wf[nt * 32];
            asm volatile(
                "mma.sync.aligned.m16n8k16.row.col.f32.f16.f16.f32 "
                "{%0,%1,%2,%3}, {%4,%5,%6,%7}, {%8,%9}, {%0,%1,%2,%3};"
                : "+f"(d[nt][0]), "+f"(d[nt][1]), "+f"(d[nt][2]), "+f"(d[nt][3])
                : "r"(a0), "r"(a1), "r"(a2), "r"(a3), "r"(b.x), "r"(b.y));
        }
    }

    unsigned* zr0 = &g_zh[(size_t)(M0 + gid) * 32];
    unsigned* zr1 = &g_zh[(size_t)(M0 + 8 + gid) * 32];
    #pragma unroll
    for (int nt = 0; nt < 8; ++nt) {
        __half2 p0 = __floats2half2_rn(d[nt][0], d[nt][1]);
        __half2 p1 = __floats2half2_rn(d[nt][2], d[nt][3]);
        zr0[nt * 4 + tig] = *(unsigned*)&p0;
        zr1[nt * 4 + tig] = *(unsigned*)&p1;
    }
}

// ---------------- K2: edge pass (4 edges/thread): w = ezs[s], drop into dst bucket -----
__global__ void k_edge(const int* __restrict__ src, const int* __restrict__ dst) {
    int i = blockIdx.x * blockDim.x + threadIdx.x;   // quad index
    if (i * 4 >= N_EDGES) return;
    int4 s4 = ((const int4*)src)[i];
    int4 d4 = ((const int4*)dst)[i];
    float w0 = g_ezs[s4.x];
    float w1 = g_ezs[s4.y];
    float w2 = g_ezs[s4.z];
    float w3 = g_ezs[s4.w];
    int p0 = atomicAdd(&g_cnt[d4.x], 1);
    int p1 = atomicAdd(&g_cnt[d4.y], 1);
    int p2 = atomicAdd(&g_cnt[d4.z], 1);
    int p3 = atomicAdd(&g_cnt[d4.w], 1);
    g_perm[d4.x * CAP + p0] = make_int2(s4.x, __float_as_int(w0));
    g_perm[d4.y * CAP + p1] = make_int2(s4.y, __float_as_int(w1));
    g_perm[d4.z * CAP + p2] = make_int2(s4.z, __float_as_int(w2));
    g_perm[d4.w * CAP + p3] = make_int2(s4.w, __float_as_int(w3));
}

// ---------------- K3: warp-per-node accumulate (fp32 quad loop, known-good) ----------
__global__ __launch_bounds__(256) void k_accum(float* __restrict__ out) {
    int gw   = (blockIdx.x * 256 + threadIdx.x) >> 5;
    int lane = threadIdx.x & 31;
    if (gw >= N_NODES) return;
    int cnt  = g_cnt[gw];
    const int2* bucket = g_perm + (size_t)gw * CAP;
    const int4* b4     = (const int4*)bucket;

    float acc0 = 0.0f, acc1 = 0.0f, den = 0.0f;
    int nq = cnt >> 2;
    #pragma unroll 1
    for (int q = 0; q < nq; ++q) {
        int4 ba = b4[2 * q];
        int4 bb = b4[2 * q + 1];
        unsigned u0 = g_zh[ba.x * 32 + lane];
        unsigned u1 = g_zh[ba.z * 32 + lane];
        unsigned u2 = g_zh[bb.x * 32 + lane];
        unsigned u3 = g_zh[bb.z * 32 + lane];
        float w0 = __int_as_float(ba.y), w1 = __int_as_float(ba.w);
        float w2 = __int_as_float(bb.y), w3 = __int_as_float(bb.w);
        float2 f0 = __half22float2(*(__half2*)&u0);
        float2 f1 = __half22float2(*(__half2*)&u1);
        float2 f2 = __half22float2(*(__half2*)&u2);
        float2 f3 = __half22float2(*(__half2*)&u3);
        acc0 = fmaf(w0, f0.x, acc0); acc1 = fmaf(w0, f0.y, acc1);
        acc0 = fmaf(w1, f1.x, acc0); acc1 = fmaf(w1, f1.y, acc1);
        acc0 = fmaf(w2, f2.x, acc0); acc1 = fmaf(w2, f2.y, acc1);
        acc0 = fmaf(w3, f3.x, acc0); acc1 = fmaf(w3, f3.y, acc1);
        den += (w0 + w1) + (w2 + w3);
    }
    for (int j = nq << 2; j < cnt; ++j) {
        int2 p = bucket[j];
        unsigned u = g_zh[p.x * 32 + lane];
        float w = __int_as_float(p.y);
        float2 f = __half22float2(*(__half2*)&u);
        acc0 = fmaf(w, f.x, acc0); acc1 = fmaf(w, f.y, acc1);
        den += w;
    }
    float inv = (cnt > 0) ? (1.0f / den) : 0.0f;
    float2 res = make_float2(acc0 * inv, acc1 * inv);
    ((float2*)out)[(size_t)gw * 32 + lane] = res;
}

// ---------------- launch: fork gemm onto a side branch, join before accum -------------
struct AsyncCtx {
    cudaStream_t s2;
    cudaEvent_t  ev_fork, ev_join;
    AsyncCtx() {
        cudaStreamCreateWithFlags(&s2, cudaStreamNonBlocking);
        cudaEventCreateWithFlags(&ev_fork, cudaEventDisableTiming);
        cudaEventCreateWithFlags(&ev_join, cudaEventDisableTiming);
    }
};

extern "C" void kernel_launch(void* const* d_in, const int* in_sizes, int n_in,
                              void* d_out, int out_size) {
    const float* h   = (const float*)d_in[0];
    const float* W   = (const float*)d_in[1];
    const float* a   = (const float*)d_in[2];
    const int*   src = (const int*)d_in[3];
    const int*   dst = (const int*)d_in[4];
    float* out = (float*)d_out;
    (void)in_sizes; (void)n_in; (void)out_size;

    static AsyncCtx ctx;                               // created on first (uncaptured) call

    k_prep<<<9, 256>>>(W, a);                          // W frags + va        [stream 0]

    // fork: gemm on side stream (depends on prep)
    cudaEventRecord(ctx.ev_fork, 0);
    cudaStreamWaitEvent(ctx.s2, ctx.ev_fork, 0);
    k_gemm<<<(N_NODES + 127) / 128, 256, 0, ctx.s2>>>(h);          // z only   [stream s2]
    cudaEventRecord(ctx.ev_join, ctx.s2);

    // main branch: logits -> edge buckets
    k_logit<<<(N_NODES * 32 + 255) / 256, 256>>>(h);               // ezs + cnt=0
    k_edge<<<((N_EDGES / 4) + 255) / 256, 256>>>(src, dst);        // 4 edges / thread

    // join: accum needs z (gemm) + buckets (edge)
    cudaStreamWaitEvent(0, ctx.ev_join, 0);
    k_accum<<<(N_NODES * 32 + 255) / 256, 256>>>(out);
}

// round 15
// speedup vs baseline: 1.0213x; 1.0213x over previous
#include <cuda_runtime.h>
#include <cuda_fp16.h>
#include <cstdint>

#define N_NODES 100000
#define N_EDGES 3200000
#define D_IN    128
#define D_OUT   64
#define CAP     96      // max in-degree bucket capacity (actual max ~58 for Poisson(32))

// ---------------- scratch (static device globals; no allocation) ----------------
__device__ unsigned g_yh  [(size_t)N_NODES * 32];      // y = ezs*z as half2, 12.8 MB
__device__ float    g_ezs [N_NODES];                   // exp(h . va)  (zd cancels in softmax)
__device__ int      g_cnt [N_NODES];                   // bucket fill counts
__device__ int      g_srcp[(size_t)N_NODES * CAP];     // src-only buckets, 38.4 MB
__device__ uint2    g_wf  [8 * 8 * 32];                // W as HMMA B-fragments [kstep][ntile][lane]
__device__ float    g_va  [D_IN];                      // W @ a[:64]

// ---------------- K0: prep — W fragments + projected attention vector ----------------
__global__ void k_prep(const float* __restrict__ W, const float* __restrict__ a) {
    if (blockIdx.x < 8) {
        int t = blockIdx.x * 256 + threadIdx.x;       // 0..2047 = [kstep][ntile][lane]
        int lane = t & 31;
        int gid = lane >> 2, tig = lane & 3;
        int rest = t >> 5;
        int ntile = rest & 7, kstep = rest >> 3;
        int k0 = kstep * 16 + tig * 2;
        int n  = ntile * 8 + gid;
        __half2 b0 = __floats2half2_rn(W[k0 * 64 + n],       W[(k0 + 1) * 64 + n]);
        __half2 b1 = __floats2half2_rn(W[(k0 + 8) * 64 + n], W[(k0 + 9) * 64 + n]);
        g_wf[t] = make_uint2(*(unsigned*)&b0, *(unsigned*)&b1);
    } else {
        int k = threadIdx.x;
        if (k < D_IN) {
            float sa = 0.0f;
            #pragma unroll 8
            for (int n = 0; n < 64; ++n)
                sa = fmaf(W[k * 64 + n], a[n], sa);
            g_va[k] = sa;
        }
    }
}

// ---------------- K1: y = exp(h.va) * (h @ W) via HMMA; store ezs; zero cnt ----------
// 8 warps/block, warp = 16 nodes x 64 cols. A frags straight from gmem (fp32->f16x2).
__global__ __launch_bounds__(256) void k_gemm(const float* __restrict__ h) {
    int warp = threadIdx.x >> 5, lane = threadIdx.x & 31;
    int gid = lane >> 2, tig = lane & 3;
    int M0 = blockIdx.x * 128 + warp * 16;
    if (M0 >= N_NODES) return;                         // 100000 % 16 == 0: full tiles only
    const float* rowA = h + (size_t)(M0 + gid) * D_IN;
    const float* rowB = h + (size_t)(M0 + 8 + gid) * D_IN;

    float d[8][4] = {};                                // [ntile][c0..c3]
    float zsA = 0.0f, zsB = 0.0f;

    #pragma unroll
    for (int ks = 0; ks < 8; ++ks) {
        int kA = ks * 16 + tig * 2;
        float2 fa0 = *(const float2*)&rowA[kA];        // A[gid][kA..+1]
        float2 fa1 = *(const float2*)&rowB[kA];        // A[gid+8][kA..+1]
        float2 fa2 = *(const float2*)&rowA[kA + 8];    // A[gid][kA+8..+9]
        float2 fa3 = *(const float2*)&rowB[kA + 8];    // A[gid+8][kA+8..+9]
        // exact fp32 logit partial: zs = h . va
        float2 vaL = *(const float2*)&g_va[kA];
        float2 vaH = *(const float2*)&g_va[kA + 8];
        zsA = fmaf(fa0.x, vaL.x, fmaf(fa0.y, vaL.y, fmaf(fa2.x, vaH.x, fmaf(fa2.y, vaH.y, zsA))));
        zsB = fmaf(fa1.x, vaL.x, fmaf(fa1.y, vaL.y, fmaf(fa3.x, vaH.x, fmaf(fa3.y, vaH.y, zsB))));
        __half2 ha0 = __floats2half2_rn(fa0.x, fa0.y);
        __half2 ha1 = __floats2half2_rn(fa1.x, fa1.y);
        __half2 ha2 = __floats2half2_rn(fa2.x, fa2.y);
        __half2 ha3 = __floats2half2_rn(fa3.x, fa3.y);
        unsigned a0 = *(unsigned*)&ha0, a1 = *(unsigned*)&ha1;
        unsigned a2 = *(unsigned*)&ha2, a3 = *(unsigned*)&ha3;
        const uint2* wf = &g_wf[ks * 256 + lane];
        #pragma unroll
        for (int nt = 0; nt < 8; ++nt) {
            uint2 b = wf[nt * 32];
            asm volatile(
                "mma.sync.aligned.m16n8k16.row.col.f32.f16.f16.f32 "
                "{%0,%1,%2,%3}, {%4,%5,%6,%7}, {%8,%9}, {%0,%1,%2,%3};"
                : "+f"(d[nt][0]), "+f"(d[nt][1]), "+f"(d[nt][2]), "+f"(d[nt][3])
                : "r"(a0), "r"(a1), "r"(a2), "r"(a3), "r"(b.x), "r"(b.y));
        }
    }

    // reduce logits across the 4-lane tig group (all lanes get the sum)
    zsA += __shfl_xor_sync(0xffffffffu, zsA, 1); zsA += __shfl_xor_sync(0xffffffffu, zsA, 2);
    zsB += __shfl_xor_sync(0xffffffffu, zsB, 1); zsB += __shfl_xor_sync(0xffffffffu, zsB, 2);
    float ezsA = __expf(zsA);
    float ezsB = __expf(zsB);

    // y store: row M0+gid cols nt*8+tig*2(,+1) -> word nt*4+tig; row M0+8+gid from c2,c3
    unsigned* yr0 = &g_yh[(size_t)(M0 + gid) * 32];
    unsigned* yr1 = &g_yh[(size_t)(M0 + 8 + gid) * 32];
    #pragma unroll
    for (int nt = 0; nt < 8; ++nt) {
        __half2 p0 = __floats2half2_rn(d[nt][0] * ezsA, d[nt][1] * ezsA);
        __half2 p1 = __floats2half2_rn(d[nt][2] * ezsB, d[nt][3] * ezsB);
        yr0[nt * 4 + tig] = *(unsigned*)&p0;
        yr1[nt * 4 + tig] = *(unsigned*)&p1;
    }
    if (tig == 0) {
        int n1 = M0 + gid, n2 = M0 + 8 + gid;
        g_ezs[n1] = ezsA; g_cnt[n1] = 0;
        g_ezs[n2] = ezsB; g_cnt[n2] = 0;
    }
}

// ---------------- K2: edge pass (4 edges/thread): src-only bucket drop ----------------
// No weight gather at all: y is premultiplied by ezs, den recovered in accum.
__global__ void k_edge(const int* __restrict__ src, const int* __restrict__ dst) {
    int i = blockIdx.x * blockDim.x + threadIdx.x;   // quad index
    if (i * 4 >= N_EDGES) return;
    int4 s4 = ((const int4*)src)[i];
    int4 d4 = ((const int4*)dst)[i];
    int p0 = atomicAdd(&g_cnt[d4.x], 1);
    int p1 = atomicAdd(&g_cnt[d4.y], 1);
    int p2 = atomicAdd(&g_cnt[d4.z], 1);
    int p3 = atomicAdd(&g_cnt[d4.w], 1);
    g_srcp[d4.x * CAP + p0] = s4.x;
    g_srcp[d4.y * CAP + p1] = s4.y;
    g_srcp[d4.z * CAP + p2] = s4.z;
    g_srcp[d4.w * CAP + p3] = s4.w;
}

// ---------------- K3: warp-per-node accumulate: out = (sum y[src]) / (sum ezs[src]) ---
__global__ __launch_bounds__(256) void k_accum(float* __restrict__ out) {
    int gw   = (blockIdx.x * 256 + threadIdx.x) >> 5;
    int lane = threadIdx.x & 31;
    if (gw >= N_NODES) return;
    int cnt  = g_cnt[gw];
    const int* bucket = g_srcp + (size_t)gw * CAP;
    const int4* b4    = (const int4*)bucket;

    float acc0 = 0.0f, acc1 = 0.0f, den = 0.0f;
    int nq = cnt >> 2;
    #pragma unroll 1
    for (int q = 0; q < nq; ++q) {
        int4 s = b4[q];                                // 4 srcs, one LDG.128 per quad
        unsigned u0 = g_yh[s.x * 32 + lane];
        unsigned u1 = g_yh[s.y * 32 + lane];
        unsigned u2 = g_yh[s.z * 32 + lane];
        unsigned u3 = g_yh[s.w * 32 + lane];
        float e0 = g_ezs[s.x];                         // warp-uniform gathers (L2/L1 hot)
        float e1 = g_ezs[s.y];
        float e2 = g_ezs[s.z];
        float e3 = g_ezs[s.w];
        float2 f0 = __half22float2(*(__half2*)&u0);
        float2 f1 = __half22float2(*(__half2*)&u1);
        float2 f2 = __half22float2(*(__half2*)&u2);
        float2 f3 = __half22float2(*(__half2*)&u3);
        acc0 += (f0.x + f1.x) + (f2.x + f3.x);
        acc1 += (f0.y + f1.y) + (f2.y + f3.y);
        den  += (e0 + e1) + (e2 + e3);
    }
    for (int j = nq << 2; j < cnt; ++j) {
        int s = bucket[j];
        unsigned u = g_yh[s * 32 + lane];
        float2 f = __half22float2(*(__half2*)&u);
        acc0 += f.x; acc1 += f.y;
        den  += g_ezs[s];
    }
    float inv = (cnt > 0) ? (1.0f / den) : 0.0f;
    float2 res = make_float2(acc0 * inv, acc1 * inv);
    ((float2*)out)[(size_t)gw * 32 + lane] = res;
}

// ---------------- launch (single stream; fork reverted after R13 FAIL) ----------------
extern "C" void kernel_launch(void* const* d_in, const int* in_sizes, int n_in,
                              void* d_out, int out_size) {
    const float* h   = (const float*)d_in[0];
    const float* W   = (const float*)d_in[1];
    const float* a   = (const float*)d_in[2];
    const int*   src = (const int*)d_in[3];
    const int*   dst = (const int*)d_in[4];
    float* out = (float*)d_out;
    (void)in_sizes; (void)n_in; (void)out_size;

    k_prep<<<9, 256>>>(W, a);                                  // W frags + va
    k_gemm<<<(N_NODES + 127) / 128, 256>>>(h);                 // HMMA; y=ezs*z; zero cnt
    k_edge<<<((N_EDGES / 4) + 255) / 256, 256>>>(src, dst);    // src-only buckets
    k_accum<<<(N_NODES * 32 + 255) / 256, 256>>>(out);
}

// round 16
// speedup vs baseline: 1.0659x; 1.0437x over previous
#include <cuda_runtime.h>
#include <cuda_fp16.h>
#include <cstdint>

#define N_NODES 100000
#define N_EDGES 3200000
#define D_IN    128
#define D_OUT   64
#define CAP     96      // max in-degree bucket capacity (actual max ~58 for Poisson(32))

// ---------------- scratch (static device globals; no allocation) ----------------
__device__ unsigned g_yh  [(size_t)N_NODES * 32];      // y = ezs*z as half2, 12.8 MB
__device__ float    g_ezs [N_NODES];                   // exp(h . va)  (zd cancels in softmax)
__device__ int      g_cnt [N_NODES];                   // bucket fill counts
__device__ int      g_srcp[(size_t)N_NODES * CAP];     // src-only buckets, 38.4 MB
__device__ uint2    g_wf  [8 * 8 * 32];                // W as HMMA B-fragments [kstep][ntile][lane]
__device__ float    g_va  [D_IN];                      // W @ a[:64]

// ---------------- K0: prep — W fragments + projected attention vector ----------------
__global__ void k_prep(const float* __restrict__ W, const float* __restrict__ a) {
    if (blockIdx.x < 8) {
        int t = blockIdx.x * 256 + threadIdx.x;       // 0..2047 = [kstep][ntile][lane]
        int lane = t & 31;
        int gid = lane >> 2, tig = lane & 3;
        int rest = t >> 5;
        int ntile = rest & 7, kstep = rest >> 3;
        int k0 = kstep * 16 + tig * 2;
        int n  = ntile * 8 + gid;
        __half2 b0 = __floats2half2_rn(W[k0 * 64 + n],       W[(k0 + 1) * 64 + n]);
        __half2 b1 = __floats2half2_rn(W[(k0 + 8) * 64 + n], W[(k0 + 9) * 64 + n]);
        g_wf[t] = make_uint2(*(unsigned*)&b0, *(unsigned*)&b1);
    } else {
        int k = threadIdx.x;
        if (k < D_IN) {
            float sa = 0.0f;
            #pragma unroll 8
            for (int n = 0; n < 64; ++n)
                sa = fmaf(W[k * 64 + n], a[n], sa);
            g_va[k] = sa;
        }
    }
}

// ---------------- K1: y = exp(h.va) * (h @ W) via HMMA; store ezs; zero cnt ----------
// 8 warps/block, warp = 16 nodes x 64 cols. A frags straight from gmem (fp32->f16x2).
__global__ __launch_bounds__(256) void k_gemm(const float* __restrict__ h) {
    int warp = threadIdx.x >> 5, lane = threadIdx.x & 31;
    int gid = lane >> 2, tig = lane & 3;
    int M0 = blockIdx.x * 128 + warp * 16;
    if (M0 >= N_NODES) return;                         // 100000 % 16 == 0: full tiles only
    const float* rowA = h + (size_t)(M0 + gid) * D_IN;
    const float* rowB = h + (size_t)(M0 + 8 + gid) * D_IN;

    float d[8][4] = {};                                // [ntile][c0..c3]
    float zsA = 0.0f, zsB = 0.0f;

    #pragma unroll
    for (int ks = 0; ks < 8; ++ks) {
        int kA = ks * 16 + tig * 2;
        float2 fa0 = *(const float2*)&rowA[kA];        // A[gid][kA..+1]
        float2 fa1 = *(const float2*)&rowB[kA];        // A[gid+8][kA..+1]
        float2 fa2 = *(const float2*)&rowA[kA + 8];    // A[gid][kA+8..+9]
        float2 fa3 = *(const float2*)&rowB[kA + 8];    // A[gid+8][kA+8..+9]
        // exact fp32 logit partial: zs = h . va
        float2 vaL = *(const float2*)&g_va[kA];
        float2 vaH = *(const float2*)&g_va[kA + 8];
        zsA = fmaf(fa0.x, vaL.x, fmaf(fa0.y, vaL.y, fmaf(fa2.x, vaH.x, fmaf(fa2.y, vaH.y, zsA))));
        zsB = fmaf(fa1.x, vaL.x, fmaf(fa1.y, vaL.y, fmaf(fa3.x, vaH.x, fmaf(fa3.y, vaH.y, zsB))));
        __half2 ha0 = __floats2half2_rn(fa0.x, fa0.y);
        __half2 ha1 = __floats2half2_rn(fa1.x, fa1.y);
        __half2 ha2 = __floats2half2_rn(fa2.x, fa2.y);
        __half2 ha3 = __floats2half2_rn(fa3.x, fa3.y);
        unsigned a0 = *(unsigned*)&ha0, a1 = *(unsigned*)&ha1;
        unsigned a2 = *(unsigned*)&ha2, a3 = *(unsigned*)&ha3;
        const uint2* wf = &g_wf[ks * 256 + lane];
        #pragma unroll
        for (int nt = 0; nt < 8; ++nt) {
            uint2 b = wf[nt * 32];
            asm volatile(
                "mma.sync.aligned.m16n8k16.row.col.f32.f16.f16.f32 "
                "{%0,%1,%2,%3}, {%4,%5,%6,%7}, {%8,%9}, {%0,%1,%2,%3};"
                : "+f"(d[nt][0]), "+f"(d[nt][1]), "+f"(d[nt][2]), "+f"(d[nt][3])
                : "r"(a0), "r"(a1), "r"(a2), "r"(a3), "r"(b.x), "r"(b.y));
        }
    }

    // reduce logits across the 4-lane tig group (all lanes get the sum)
    zsA += __shfl_xor_sync(0xffffffffu, zsA, 1); zsA += __shfl_xor_sync(0xffffffffu, zsA, 2);
    zsB += __shfl_xor_sync(0xffffffffu, zsB, 1); zsB += __shfl_xor_sync(0xffffffffu, zsB, 2);
    float ezsA = __expf(zsA);
    float ezsB = __expf(zsB);

    // y store: row M0+gid cols nt*8+tig*2(,+1) -> word nt*4+tig; row M0+8+gid from c2,c3
    unsigned* yr0 = &g_yh[(size_t)(M0 + gid) * 32];
    unsigned* yr1 = &g_yh[(size_t)(M0 + 8 + gid) * 32];
    #pragma unroll
    for (int nt = 0; nt < 8; ++nt) {
        __half2 p0 = __floats2half2_rn(d[nt][0] * ezsA, d[nt][1] * ezsA);
        __half2 p1 = __floats2half2_rn(d[nt][2] * ezsB, d[nt][3] * ezsB);
        yr0[nt * 4 + tig] = *(unsigned*)&p0;
        yr1[nt * 4 + tig] = *(unsigned*)&p1;
    }
    if (tig == 0) {
        int n1 = M0 + gid, n2 = M0 + 8 + gid;
        g_ezs[n1] = ezsA; g_cnt[n1] = 0;
        g_ezs[n2] = ezsB; g_cnt[n2] = 0;
    }
}

// ---------------- K2: edge pass (4 edges/thread): src-only bucket drop ----------------
// No weight gather at all: y is premultiplied by ezs, den recovered in accum phase 1.
__global__ void k_edge(const int* __restrict__ src, const int* __restrict__ dst) {
    int i = blockIdx.x * blockDim.x + threadIdx.x;   // quad index
    if (i * 4 >= N_EDGES) return;
    int4 s4 = ((const int4*)src)[i];
    int4 d4 = ((const int4*)dst)[i];
    int p0 = atomicAdd(&g_cnt[d4.x], 1);
    int p1 = atomicAdd(&g_cnt[d4.y], 1);
    int p2 = atomicAdd(&g_cnt[d4.z], 1);
    int p3 = atomicAdd(&g_cnt[d4.w], 1);
    g_srcp[d4.x * CAP + p0] = s4.x;
    g_srcp[d4.y * CAP + p1] = s4.y;
    g_srcp[d4.z * CAP + p2] = s4.z;
    g_srcp[d4.w * CAP + p3] = s4.w;
}

// ---------------- K3: warp-per-node accumulate ----------------------------------------
// Phase 1: den = sum ezs[src] via lane-parallel gather + warp reduce (~1 step/node).
// Phase 2: out-row sum of y[src] rows; 5 loads/quad (1 bucket LDG.128 + 4 y LDG).
__global__ __launch_bounds__(256) void k_accum(float* __restrict__ out) {
    int gw   = (blockIdx.x * 256 + threadIdx.x) >> 5;
    int lane = threadIdx.x & 31;
    if (gw >= N_NODES) return;
    int cnt  = g_cnt[gw];
    const int* bucket = g_srcp + (size_t)gw * CAP;
    const int4* b4    = (const int4*)bucket;

    // phase 1: denominator (lane-parallel)
    float den = 0.0f;
    for (int j = lane; j < cnt; j += 32)
        den += g_ezs[bucket[j]];
    #pragma unroll
    for (int o = 16; o > 0; o >>= 1)
        den += __shfl_xor_sync(0xffffffffu, den, o);

    // phase 2: numerator (y rows premultiplied by ezs)
    float acc0 = 0.0f, acc1 = 0.0f;
    int nq = cnt >> 2;
    #pragma unroll 1
    for (int q = 0; q < nq; ++q) {
        int4 s = b4[q];                                // 4 srcs, one LDG.128 per quad
        unsigned u0 = g_yh[s.x * 32 + lane];
        unsigned u1 = g_yh[s.y * 32 + lane];
        unsigned u2 = g_yh[s.z * 32 + lane];
        unsigned u3 = g_yh[s.w * 32 + lane];
        float2 f0 = __half22float2(*(__half2*)&u0);
        float2 f1 = __half22float2(*(__half2*)&u1);
        float2 f2 = __half22float2(*(__half2*)&u2);
        float2 f3 = __half22float2(*(__half2*)&u3);
        acc0 += (f0.x + f1.x) + (f2.x + f3.x);
        acc1 += (f0.y + f1.y) + (f2.y + f3.y);
    }
    for (int j = nq << 2; j < cnt; ++j) {
        unsigned u = g_yh[bucket[j] * 32 + lane];
        float2 f = __half22float2(*(__half2*)&u);
        acc0 += f.x; acc1 += f.y;
    }
    float inv = (cnt > 0) ? (1.0f / den) : 0.0f;
    float2 res = make_float2(acc0 * inv, acc1 * inv);
    ((float2*)out)[(size_t)gw * 32 + lane] = res;
}

// ---------------- launch ----------------
extern "C" void kernel_launch(void* const* d_in, const int* in_sizes, int n_in,
                              void* d_out, int out_size) {
    const float* h   = (const float*)d_in[0];
    const float* W   = (const float*)d_in[1];
    const float* a   = (const float*)d_in[2];
    const int*   src = (const int*)d_in[3];
    const int*   dst = (const int*)d_in[4];
    float* out = (float*)d_out;
    (void)in_sizes; (void)n_in; (void)out_size;

    k_prep<<<9, 256>>>(W, a);                                  // W frags + va
    k_gemm<<<(N_NODES + 127) / 128, 256>>>(h);                 // HMMA; y=ezs*z; zero cnt
    k_edge<<<((N_EDGES / 4) + 255) / 256, 256>>>(src, dst);    // src-only buckets
    k_accum<<<(N_NODES * 32 + 255) / 256, 256>>>(out);
}

// round 17
// speedup vs baseline: 1.1116x; 1.0428x over previous
#include <cuda_runtime.h>
#include <cuda_fp16.h>
#include <cstdint>

#define N_NODES 100000
#define N_EDGES 3200000
#define D_IN    128
#define D_OUT   64
#define CAP     96      // max in-degree bucket capacity (actual max ~58 for Poisson(32))

// ---------------- scratch (static device globals; no allocation) ----------------
__device__ unsigned g_yh  [(size_t)N_NODES * 32];      // y = ezs*z as half2, 12.8 MB
__device__ float    g_ezs [N_NODES];                   // exp(h . va)  (zd cancels in softmax)
__device__ int      g_cnt [N_NODES];                   // bucket fill counts
__device__ int      g_srcp[(size_t)N_NODES * CAP];     // src-only buckets, 38.4 MB
__device__ uint2    g_wf  [8 * 8 * 32];                // W as HMMA B-fragments [kstep][ntile][lane]
__device__ float    g_va  [D_IN];                      // W @ a[:64]

// ---------------- K0: prep — W fragments + va + cnt zeroing ---------------------------
// blocks 0-7: wf frags; block 8: va; blocks 9+: zero g_cnt (enables edge/gemm overlap)
__global__ void k_prep(const float* __restrict__ W, const float* __restrict__ a) {
    if (blockIdx.x < 8) {
        int t = blockIdx.x * 256 + threadIdx.x;       // 0..2047 = [kstep][ntile][lane]
        int lane = t & 31;
        int gid = lane >> 2, tig = lane & 3;
        int rest = t >> 5;
        int ntile = rest & 7, kstep = rest >> 3;
        int k0 = kstep * 16 + tig * 2;
        int n  = ntile * 8 + gid;
        __half2 b0 = __floats2half2_rn(W[k0 * 64 + n],       W[(k0 + 1) * 64 + n]);
        __half2 b1 = __floats2half2_rn(W[(k0 + 8) * 64 + n], W[(k0 + 9) * 64 + n]);
        g_wf[t] = make_uint2(*(unsigned*)&b0, *(unsigned*)&b1);
    } else if (blockIdx.x == 8) {
        int k = threadIdx.x;
        if (k < D_IN) {
            float sa = 0.0f;
            #pragma unroll 8
            for (int n = 0; n < 64; ++n)
                sa = fmaf(W[k * 64 + n], a[n], sa);
            g_va[k] = sa;
        }
    } else {
        int i = (blockIdx.x - 9) * 256 + threadIdx.x;
        if (i < N_NODES) g_cnt[i] = 0;
    }
}

// ---------------- K1: y = exp(h.va) * (h @ W) via HMMA; store ezs ---------------------
// 8 warps/block, warp = 16 nodes x 64 cols. A frags straight from gmem (fp32->f16x2).
__global__ __launch_bounds__(256) void k_gemm(const float* __restrict__ h) {
    int warp = threadIdx.x >> 5, lane = threadIdx.x & 31;
    int gid = lane >> 2, tig = lane & 3;
    int M0 = blockIdx.x * 128 + warp * 16;
    if (M0 >= N_NODES) return;                         // 100000 % 16 == 0: full tiles only
    const float* rowA = h + (size_t)(M0 + gid) * D_IN;
    const float* rowB = h + (size_t)(M0 + 8 + gid) * D_IN;

    float d[8][4] = {};                                // [ntile][c0..c3]
    float zsA = 0.0f, zsB = 0.0f;

    #pragma unroll
    for (int ks = 0; ks < 8; ++ks) {
        int kA = ks * 16 + tig * 2;
        float2 fa0 = *(const float2*)&rowA[kA];        // A[gid][kA..+1]
        float2 fa1 = *(const float2*)&rowB[kA];        // A[gid+8][kA..+1]
        float2 fa2 = *(const float2*)&rowA[kA + 8];    // A[gid][kA+8..+9]
        float2 fa3 = *(const float2*)&rowB[kA + 8];    // A[gid+8][kA+8..+9]
        // exact fp32 logit partial: zs = h . va
        float2 vaL = *(const float2*)&g_va[kA];
        float2 vaH = *(const float2*)&g_va[kA + 8];
        zsA = fmaf(fa0.x, vaL.x, fmaf(fa0.y, vaL.y, fmaf(fa2.x, vaH.x, fmaf(fa2.y, vaH.y, zsA))));
        zsB = fmaf(fa1.x, vaL.x, fmaf(fa1.y, vaL.y, fmaf(fa3.x, vaH.x, fmaf(fa3.y, vaH.y, zsB))));
        __half2 ha0 = __floats2half2_rn(fa0.x, fa0.y);
        __half2 ha1 = __floats2half2_rn(fa1.x, fa1.y);
        __half2 ha2 = __floats2half2_rn(fa2.x, fa2.y);
        __half2 ha3 = __floats2half2_rn(fa3.x, fa3.y);
        unsigned a0 = *(unsigned*)&ha0, a1 = *(unsigned*)&ha1;
        unsigned a2 = *(unsigned*)&ha2, a3 = *(unsigned*)&ha3;
        const uint2* wf = &g_wf[ks * 256 + lane];
        #pragma unroll
        for (int nt = 0; nt < 8; ++nt) {
            uint2 b = wf[nt * 32];
            asm volatile(
                "mma.sync.aligned.m16n8k16.row.col.f32.f16.f16.f32 "
                "{%0,%1,%2,%3}, {%4,%5,%6,%7}, {%8,%9}, {%0,%1,%2,%3};"
                : "+f"(d[nt][0]), "+f"(d[nt][1]), "+f"(d[nt][2]), "+f"(d[nt][3])
                : "r"(a0), "r"(a1), "r"(a2), "r"(a3), "r"(b.x), "r"(b.y));
        }
    }

    // reduce logits across the 4-lane tig group (all lanes get the sum)
    zsA += __shfl_xor_sync(0xffffffffu, zsA, 1); zsA += __shfl_xor_sync(0xffffffffu, zsA, 2);
    zsB += __shfl_xor_sync(0xffffffffu, zsB, 1); zsB += __shfl_xor_sync(0xffffffffu, zsB, 2);
    float ezsA = __expf(zsA);
    float ezsB = __expf(zsB);

    // y store: row M0+gid cols nt*8+tig*2(,+1) -> word nt*4+tig; row M0+8+gid from c2,c3
    unsigned* yr0 = &g_yh[(size_t)(M0 + gid) * 32];
    unsigned* yr1 = &g_yh[(size_t)(M0 + 8 + gid) * 32];
    #pragma unroll
    for (int nt = 0; nt < 8; ++nt) {
        __half2 p0 = __floats2half2_rn(d[nt][0] * ezsA, d[nt][1] * ezsA);
        __half2 p1 = __floats2half2_rn(d[nt][2] * ezsB, d[nt][3] * ezsB);
        yr0[nt * 4 + tig] = *(unsigned*)&p0;
        yr1[nt * 4 + tig] = *(unsigned*)&p1;
    }
    if (tig == 0) {
        g_ezs[M0 + gid]     = ezsA;
        g_ezs[M0 + 8 + gid] = ezsB;
    }
}

// ---------------- K2: edge pass (4 edges/thread): src-only bucket drop ----------------
// Independent of k_gemm (only needs cnt zeroed by prep) -> runs concurrently with it.
__global__ void k_edge(const int* __restrict__ src, const int* __restrict__ dst) {
    int i = blockIdx.x * blockDim.x + threadIdx.x;   // quad index
    if (i * 4 >= N_EDGES) return;
    int4 s4 = ((const int4*)src)[i];
    int4 d4 = ((const int4*)dst)[i];
    int p0 = atomicAdd(&g_cnt[d4.x], 1);
    int p1 = atomicAdd(&g_cnt[d4.y], 1);
    int p2 = atomicAdd(&g_cnt[d4.z], 1);
    int p3 = atomicAdd(&g_cnt[d4.w], 1);
    g_srcp[d4.x * CAP + p0] = s4.x;
    g_srcp[d4.y * CAP + p1] = s4.y;
    g_srcp[d4.z * CAP + p2] = s4.z;
    g_srcp[d4.w * CAP + p3] = s4.w;
}

// ---------------- K3: warp-per-node accumulate ----------------------------------------
// Phase 1: den = sum ezs[src] via lane-parallel gather + warp reduce.
// Phase 2: out-row sum of y[src] rows; 5 loads/quad (1 bucket LDG.128 + 4 y LDG).
__global__ __launch_bounds__(256) void k_accum(float* __restrict__ out) {
    int gw   = (blockIdx.x * 256 + threadIdx.x) >> 5;
    int lane = threadIdx.x & 31;
    if (gw >= N_NODES) return;
    int cnt  = g_cnt[gw];
    const int* bucket = g_srcp + (size_t)gw * CAP;
    const int4* b4    = (const int4*)bucket;

    // phase 1: denominator (lane-parallel)
    float den = 0.0f;
    for (int j = lane; j < cnt; j += 32)
        den += g_ezs[bucket[j]];
    #pragma unroll
    for (int o = 16; o > 0; o >>= 1)
        den += __shfl_xor_sync(0xffffffffu, den, o);

    // phase 2: numerator (y rows premultiplied by ezs)
    float acc0 = 0.0f, acc1 = 0.0f;
    int nq = cnt >> 2;
    #pragma unroll 1
    for (int q = 0; q < nq; ++q) {
        int4 s = b4[q];                                // 4 srcs, one LDG.128 per quad
        unsigned u0 = g_yh[s.x * 32 + lane];
        unsigned u1 = g_yh[s.y * 32 + lane];
        unsigned u2 = g_yh[s.z * 32 + lane];
        unsigned u3 = g_yh[s.w * 32 + lane];
        float2 f0 = __half22float2(*(__half2*)&u0);
        float2 f1 = __half22float2(*(__half2*)&u1);
        float2 f2 = __half22float2(*(__half2*)&u2);
        float2 f3 = __half22float2(*(__half2*)&u3);
        acc0 += (f0.x + f1.x) + (f2.x + f3.x);
        acc1 += (f0.y + f1.y) + (f2.y + f3.y);
    }
    for (int j = nq << 2; j < cnt; ++j) {
        unsigned u = g_yh[bucket[j] * 32 + lane];
        float2 f = __half22float2(*(__half2*)&u);
        acc0 += f.x; acc1 += f.y;
    }
    float inv = (cnt > 0) ? (1.0f / den) : 0.0f;
    float2 res = make_float2(acc0 * inv, acc1 * inv);
    ((float2*)out)[(size_t)gw * 32 + lane] = res;
}

// ---------------- launch: edge (main) || gemm (side), join before accum ---------------
struct AsyncCtx {
    cudaStream_t s2;
    cudaEvent_t  ev_fork, ev_join;
    AsyncCtx() {
        cudaStreamCreateWithFlags(&s2, cudaStreamNonBlocking);
        cudaEventCreateWithFlags(&ev_fork, cudaEventDisableTiming);
        cudaEventCreateWithFlags(&ev_join, cudaEventDisableTiming);
    }
};

extern "C" void kernel_launch(void* const* d_in, const int* in_sizes, int n_in,
                              void* d_out, int out_size) {
    const float* h   = (const float*)d_in[0];
    const float* W   = (const float*)d_in[1];
    const float* a   = (const float*)d_in[2];
    const int*   src = (const int*)d_in[3];
    const int*   dst = (const int*)d_in[4];
    float* out = (float*)d_out;
    (void)in_sizes; (void)n_in; (void)out_size;

    static AsyncCtx ctx;                               // created on first (uncaptured) call

    k_prep<<<9 + (N_NODES + 255) / 256, 256>>>(W, a);  // wf + va + cnt=0

    // fork: gemm (tensor/L1-bound) beside edge (L2-latency-bound, issue 2.4%)
    cudaEventRecord(ctx.ev_fork, 0);
    cudaStreamWaitEvent(ctx.s2, ctx.ev_fork, 0);
    k_gemm<<<(N_NODES + 127) / 128, 256, 0, ctx.s2>>>(h);
    cudaEventRecord(ctx.ev_join, ctx.s2);

    k_edge<<<((N_EDGES / 4) + 255) / 256, 256>>>(src, dst);    // main stream

    // join: accum needs y/ezs (gemm) + buckets (edge)
    cudaStreamWaitEvent(0, ctx.ev_join, 0);
    k_accum<<<(N_NODES * 32 + 255) / 256, 256>>>(out);
}